// round 1
// baseline (speedup 1.0000x reference)
#include <cuda_runtime.h>

#define HH 512
#define WW 512
#define BB 2
#define FINF 1e12f

// Scratch: row-pass squared distances. plane 0 = dist^2 to nearest fg(1) seed,
// plane 1 = dist^2 to nearest bg(0) seed.  4 MB total, static device global.
__device__ float g_rowd[2][BB][HH][WW];

// ---------------------------------------------------------------------------
// Kernel A: exact 1-D squared EDT along rows for a binary image.
// One block per (batch,row), one thread per column. Row cached in shared.
// For each pixel: own-class distance is 0; opposite-class distance is the
// outward run length to the first opposite bit (squared), or 1e12 if none.
// ---------------------------------------------------------------------------
__global__ void __launch_bounds__(WW) row_pass(const float* __restrict__ gt) {
    const int b = blockIdx.x >> 9;      // blockIdx.x = b*512 + y
    const int y = blockIdx.x & 511;
    const int x = threadIdx.x;

    __shared__ unsigned char s[WW];
    const float* row = gt + ((size_t)b * HH + y) * WW;
    const unsigned char m = (row[x] == 1.0f) ? 1u : 0u;
    s[x] = m;
    __syncthreads();

    float dopp = FINF;
    #pragma unroll 1
    for (int r = 1; r < WW; ++r) {
        const int lo = x - r, hi = x + r;
        const bool fl = (lo >= 0) && (s[lo] != m);
        const bool fh = (hi < WW) && (s[hi] != m);
        if (fl || fh) { dopp = (float)(r * r); break; }
        if (lo < 0 && hi >= WW) break;  // no opposite bit in this row
    }

    const float dfg = m ? 0.0f : dopp;  // dist^2 to nearest 1
    const float dbg = m ? dopp : 0.0f;  // dist^2 to nearest 0
    g_rowd[0][b][y][x] = dfg;
    g_rowd[1][b][y][x] = dbg;
}

// ---------------------------------------------------------------------------
// Kernel B: exact vertical min-plus with adaptive (provably exact) window:
//   best = f[i]; scan r outward while r^2 < best.
// Any j with (i-j)^2 >= best cannot beat best, so the early exit is exact.
// Loads are coalesced across x (threads in a warp share the row index trace).
// Fuses both planes and the final sqrt(neg) - sqrt(pos) epilogue.
// ---------------------------------------------------------------------------
__global__ void __launch_bounds__(WW) col_pass(float* __restrict__ out) {
    const int b = blockIdx.x >> 9;      // blockIdx.x = b*512 + i
    const int i = blockIdx.x & 511;
    const int x = threadIdx.x;

    float d[2];
    #pragma unroll
    for (int p = 0; p < 2; ++p) {
        const float* __restrict__ f = &g_rowd[p][b][0][0];
        float best = f[i * WW + x];
        #pragma unroll 1
        for (int r = 1; r < HH; ++r) {
            const float rr = (float)(r * r);
            if (rr >= best) break;
            const int up = i - r, dn = i + r;
            if (up >= 0)  best = fminf(best, f[up * WW + x] + rr);
            if (dn < HH)  best = fminf(best, f[dn * WW + x] + rr);
        }
        d[p] = best;
    }

    // neg = dist to nearest fg seed (plane 0); pos = dist to nearest bg seed.
    out[((size_t)b * HH + i) * WW + x] = sqrtf(d[0]) - sqrtf(d[1]);
}

extern "C" void kernel_launch(void* const* d_in, const int* in_sizes, int n_in,
                              void* d_out, int out_size) {
    const float* gt = (const float*)d_in[0];
    float* out = (float*)d_out;
    (void)in_sizes; (void)n_in; (void)out_size;

    row_pass<<<BB * HH, WW>>>(gt);
    col_pass<<<BB * HH, WW>>>(out);
}

// round 3
// speedup vs baseline: 1.0026x; 1.0026x over previous
#include <cuda_runtime.h>

#define HH 512
#define WW 512
#define BB 2

// Packed row-pass result: bit15 = mask (1 = fg), bits[0:15) = row distance to
// nearest OPPOSITE-class pixel (0x7fff sentinel = none in this row).
// Stored as uint32 pairs (2 pixels) for vectorized access. 1 MB total.
__device__ unsigned int g_pack[BB * HH * (WW / 2)];

// ---------------------------------------------------------------------------
// Kernel A: row pass. 2 rows per block (512 threads = 2 x 256), 2 px/thread.
// For each pixel: run-length to nearest opposite bit in its row.
// ---------------------------------------------------------------------------
__global__ void __launch_bounds__(512) row_pass(const float* __restrict__ gt) {
    const int blk = blockIdx.x;              // b*256 + yPair
    const int b = blk >> 8;
    const int rl = threadIdx.x >> 8;         // 0/1: which row of the pair
    const int tx = threadIdx.x & 255;        // pixel pair index
    const int y = ((blk & 255) << 1) + rl;

    __shared__ unsigned char s[2][WW];

    const float2 v = reinterpret_cast<const float2*>(
        gt + ((size_t)b * HH + y) * WW)[tx];
    const unsigned char m0 = (v.x == 1.0f) ? 1u : 0u;
    const unsigned char m1 = (v.y == 1.0f) ? 1u : 0u;
    const int x0 = tx * 2;
    s[rl][x0] = m0;
    s[rl][x0 + 1] = m1;
    __syncthreads();

    unsigned int d[2];
    #pragma unroll
    for (int k = 0; k < 2; ++k) {
        const int x = x0 + k;
        const unsigned char m = k ? m1 : m0;
        unsigned int dd = 0x7fffu;
        #pragma unroll 1
        for (int r = 1; r < WW; ++r) {
            const int lo = x - r, hi = x + r;
            const bool f = (lo >= 0 && s[rl][lo] != m) ||
                           (hi < WW && s[rl][hi] != m);
            if (f) { dd = (unsigned int)r; break; }
            if (lo < 0 && hi >= WW) break;
        }
        d[k] = dd | ((unsigned int)m << 15);
    }

    g_pack[((size_t)b * HH + y) * (WW / 2) + tx] = d[0] | (d[1] << 16);
}

// ---------------------------------------------------------------------------
// Kernel B: column pass, single (opposite) plane per pixel, exact adaptive
// window: best = ro^2; scan r outward while r^2 < best (provably exact:
// any j with (i-j)^2 >= best cannot improve the min).
// 2 pixels per thread via one uint32 load per row visited. Fused epilogue:
// out = (m ? -1 : +1) * sqrt(best).
// ---------------------------------------------------------------------------
__global__ void __launch_bounds__(256) col_pass(float* __restrict__ out) {
    const int b = blockIdx.x >> 9;           // blockIdx.x = b*512 + i
    const int i = blockIdx.x & 511;
    const int t = threadIdx.x;

    const unsigned int* __restrict__ col = g_pack + (size_t)b * HH * (WW / 2) + t;

    const unsigned int u = col[i * (WW / 2)];
    const unsigned int mA = (u >> 15) & 1u;
    const unsigned int mB = (u >> 31) & 1u;
    const int roA = (int)(u & 0x7fffu);
    const int roB = (int)((u >> 16) & 0x7fffu);
    float bestA = (float)(roA * roA);
    float bestB = (float)(roB * roB);

    float rr = 1.0f;   // r*r, updated incrementally: (r+1)^2 = r^2 + 2r + 1
    #pragma unroll 1
    for (int r = 1; r < HH; ++r) {
        if (rr >= bestA && rr >= bestB) break;
        const int up = i - r, dn = i + r;
        if (up >= 0) {
            const unsigned int w = col[up * (WW / 2)];
            const int ra = (int)(w & 0x7fffu);
            const int rb = (int)((w >> 16) & 0x7fffu);
            const float fa = (((w >> 15) & 1u) != mA) ? 0.0f : (float)(ra * ra);
            const float fb = (((w >> 31) & 1u) != mB) ? 0.0f : (float)(rb * rb);
            bestA = fminf(bestA, fa + rr);
            bestB = fminf(bestB, fb + rr);
        }
        if (dn < HH) {
            const unsigned int w = col[dn * (WW / 2)];
            const int ra = (int)(w & 0x7fffu);
            const int rb = (int)((w >> 16) & 0x7fffu);
            const float fa = (((w >> 15) & 1u) != mA) ? 0.0f : (float)(ra * ra);
            const float fb = (((w >> 31) & 1u) != mB) ? 0.0f : (float)(rb * rb);
            bestA = fminf(bestA, fa + rr);
            bestB = fminf(bestB, fb + rr);
        }
        rr += (float)(2 * r + 1);
    }

    float2 o;
    o.x = (mA ? -1.0f : 1.0f) * sqrtf(bestA);
    o.y = (mB ? -1.0f : 1.0f) * sqrtf(bestB);
    reinterpret_cast<float2*>(out + ((size_t)b * HH + i) * WW)[t] = o;
}

extern "C" void kernel_launch(void* const* d_in, const int* in_sizes, int n_in,
                              void* d_out, int out_size) {
    const float* gt = (const float*)d_in[0];
    float* out = (float*)d_out;
    (void)in_sizes; (void)n_in; (void)out_size;

    row_pass<<<BB * HH / 2, 512>>>(gt);
    col_pass<<<BB * HH, 256>>>(out);
}

// round 4
// speedup vs baseline: 1.1957x; 1.1925x over previous
#include <cuda_runtime.h>

#define HH 512
#define WW 512
#define BB 2

// Packed row-pass result, one uint16 per pixel:
//   bit15 = mask (1 = fg), bits[0:15) = row distance to nearest OPPOSITE-class
//   pixel (0x7fff sentinel = none in this row; both classes exist image-wide,
//   so the sentinel candidate (0x7fff^2 ~ 1.07e9) never wins vs any real
//   candidate (<= 511^2 + 511^2)).  1 MB total.
__device__ unsigned short g_pack16[BB * HH * WW];

// ---------------------------------------------------------------------------
// Kernel A: row pass via 512-bit row bitmask + word scans. 1 row per block,
// 1 pixel per thread. Nearest opposite bit found with ffs/clz on the pixel's
// own word (expected O(1)); rare fallback walks adjacent words.
// ---------------------------------------------------------------------------
__global__ void __launch_bounds__(WW) row_pass(const float* __restrict__ gt) {
    const int b = blockIdx.x >> 9;          // blockIdx.x = b*512 + y
    const int y = blockIdx.x & 511;
    const int x = threadIdx.x;

    __shared__ unsigned int sw[WW / 32];    // 16 words = 512-bit row mask

    const float v = gt[((size_t)b * HH + y) * WW + x];
    const unsigned int m = (v == 1.0f) ? 1u : 0u;
    const unsigned int bits = __ballot_sync(0xFFFFFFFFu, m != 0u);
    if ((x & 31) == 0) sw[x >> 5] = bits;
    __syncthreads();

    const unsigned int xorm = m ? 0xFFFFFFFFu : 0u;  // opp(word) = word ^ xorm
    const int w0 = x >> 5, off = x & 31;
    const unsigned int cur = sw[w0] ^ xorm;

    // Right: nearest opposite bit at position > x.
    int right = 0x7fff;
    {
        const unsigned int hi = cur & (0xFFFFFFFEu << off);  // bits > off
        if (hi) {
            right = (__ffs(hi) - 1) - off;
        } else {
            #pragma unroll 1
            for (int w = w0 + 1; w < WW / 32; ++w) {
                const unsigned int t = sw[w] ^ xorm;
                if (t) { right = (w << 5) + (__ffs(t) - 1) - x; break; }
            }
        }
    }
    // Left: nearest opposite bit at position < x.
    int left = 0x7fff;
    {
        const unsigned int lo = cur & ((1u << off) - 1u);    // bits < off
        if (lo) {
            left = off - (31 - __clz(lo));
        } else {
            #pragma unroll 1
            for (int w = w0 - 1; w >= 0; --w) {
                const unsigned int t = sw[w] ^ xorm;
                if (t) { left = x - ((w << 5) + (31 - __clz(t))); break; }
            }
        }
    }

    const unsigned int d = (unsigned int)min(min(left, right), 0x7fff);
    g_pack16[((size_t)b * HH + y) * WW + x] = (unsigned short)(d | (m << 15));
}

// ---------------------------------------------------------------------------
// Kernel B: column pass, opposite plane only, exact adaptive window
// (any j with (i-j)^2 >= best cannot improve the min), radii processed in
// PAIRS (r, r+1) with all 4 loads issued before updates -> 2x MLP on the
// serialized decide-to-continue chain. 2 pixels per thread per uint32 load.
// Fused epilogue: out = (m ? -1 : +1) * sqrt(best).
// ---------------------------------------------------------------------------
__global__ void __launch_bounds__(256) col_pass(float* __restrict__ out) {
    const int b = blockIdx.x >> 9;           // blockIdx.x = b*512 + i
    const int i = blockIdx.x & 511;
    const int t = threadIdx.x;

    const unsigned int* __restrict__ col =
        reinterpret_cast<const unsigned int*>(g_pack16) +
        (size_t)b * HH * (WW / 2) + t;

    const unsigned int u = col[i * (WW / 2)];
    const unsigned int mA = (u >> 15) & 1u;
    const unsigned int mB = (u >> 31) & 1u;
    const int roA = (int)(u & 0x7fffu);
    const int roB = (int)((u >> 16) & 0x7fffu);
    float bestA = (float)(roA * roA);
    float bestB = (float)(roB * roB);

    #pragma unroll 1
    for (int r = 1; r < HH; r += 2) {
        const float rr1 = (float)(r * r);
        if (rr1 >= bestA && rr1 >= bestB) break;
        const float rr2 = (float)((r + 1) * (r + 1));

        const int u1 = i - r, d1 = i + r, u2 = i - r - 1, d2 = i + r + 1;
        const bool bu1 = (u1 >= 0), bd1 = (d1 < HH);
        const bool bu2 = (u2 >= 0), bd2 = (d2 < HH);

        unsigned int wu1 = 0, wd1 = 0, wu2 = 0, wd2 = 0;
        if (bu1) wu1 = col[u1 * (WW / 2)];
        if (bd1) wd1 = col[d1 * (WW / 2)];
        if (bu2) wu2 = col[u2 * (WW / 2)];
        if (bd2) wd2 = col[d2 * (WW / 2)];

        if (bu1) {
            const int ra = (int)(wu1 & 0x7fffu), rb = (int)((wu1 >> 16) & 0x7fffu);
            bestA = fminf(bestA, ((((wu1 >> 15) & 1u) != mA) ? 0.0f : (float)(ra * ra)) + rr1);
            bestB = fminf(bestB, ((((wu1 >> 31) & 1u) != mB) ? 0.0f : (float)(rb * rb)) + rr1);
        }
        if (bd1) {
            const int ra = (int)(wd1 & 0x7fffu), rb = (int)((wd1 >> 16) & 0x7fffu);
            bestA = fminf(bestA, ((((wd1 >> 15) & 1u) != mA) ? 0.0f : (float)(ra * ra)) + rr1);
            bestB = fminf(bestB, ((((wd1 >> 31) & 1u) != mB) ? 0.0f : (float)(rb * rb)) + rr1);
        }
        if (bu2) {
            const int ra = (int)(wu2 & 0x7fffu), rb = (int)((wu2 >> 16) & 0x7fffu);
            bestA = fminf(bestA, ((((wu2 >> 15) & 1u) != mA) ? 0.0f : (float)(ra * ra)) + rr2);
            bestB = fminf(bestB, ((((wu2 >> 31) & 1u) != mB) ? 0.0f : (float)(rb * rb)) + rr2);
        }
        if (bd2) {
            const int ra = (int)(wd2 & 0x7fffu), rb = (int)((wd2 >> 16) & 0x7fffu);
            bestA = fminf(bestA, ((((wd2 >> 15) & 1u) != mA) ? 0.0f : (float)(ra * ra)) + rr2);
            bestB = fminf(bestB, ((((wd2 >> 31) & 1u) != mB) ? 0.0f : (float)(rb * rb)) + rr2);
        }
    }

    float2 o;
    o.x = (mA ? -1.0f : 1.0f) * sqrtf(bestA);
    o.y = (mB ? -1.0f : 1.0f) * sqrtf(bestB);
    reinterpret_cast<float2*>(out + ((size_t)b * HH + i) * WW)[t] = o;
}

extern "C" void kernel_launch(void* const* d_in, const int* in_sizes, int n_in,
                              void* d_out, int out_size) {
    const float* gt = (const float*)d_in[0];
    float* out = (float*)d_out;
    (void)in_sizes; (void)n_in; (void)out_size;

    row_pass<<<BB * HH, WW>>>(gt);
    col_pass<<<BB * HH, 256>>>(out);
}